// round 2
// baseline (speedup 1.0000x reference)
#include <cuda_runtime.h>
#include <math.h>
#include <stdint.h>

// Problem constants
#define NXC   256
#define NQC   256
#define NUC   64
#define NBATCH 32768
#define EPSC  1e-3f
#define NH    320   // NX + NQ... actually NX+NQ=512? No: H is (NX+NQ)=(256+64?) -- see below
// NOTE: X is (NX+NQ) x (NX+NQ) = 320x320?  NX=256, NQ=256 -> 512?  Recheck:
// Reference: NX, NQ, NU, NY = (256, 256, 64, 64); X: (NX+NQ, NX+NQ) = (512, 512).
// CORRECTION: NH must be 512.
#undef NH
#define NH 512

// ---------------------------------------------------------------------------
// Device scratch (static allocations only — no cudaMalloc allowed)
// ---------------------------------------------------------------------------
__device__ float g_P[NXC * NXC];          // P, then Cholesky factor L (lower)
__device__ float g_H[NH * NH];            // H = X X^T + eps I  (512x512)
__device__ float g_RHS[NXC * 512];        // [Y | Z]  (256 x 512)
__device__ float g_Wv[NQC * 320];         // [C1 | D12] rows q, K = 256+64
__device__ float g_D11t[NQC * NQC];       // D11 transposed: g_D11t[j*256+q] = D11[q][j]
__device__ float g_Wout[NXC * 576];       // [A | B1 | B2] rows x, K = 256+256+64
__device__ float g_w[(size_t)NBATCH * NQC];

// ---------------------------------------------------------------------------
// Gram kernel: out = scale * M M^T + eps I   (which==0 -> g_P(256), else g_H(512))
// ---------------------------------------------------------------------------
__global__ void gram_kernel(const float* __restrict__ M, int n, float scale, int which)
{
    __shared__ float sA[32][33];
    __shared__ float sB[32][33];
    const int tx = threadIdx.x, ty = threadIdx.y;
    const int bi = blockIdx.y * 32, bj = blockIdx.x * 32;
    float acc = 0.f;
    for (int k0 = 0; k0 < n; k0 += 32) {
        sA[ty][tx] = M[(bi + ty) * n + k0 + tx];
        sB[ty][tx] = M[(bj + ty) * n + k0 + tx];
        __syncthreads();
#pragma unroll
        for (int k = 0; k < 32; k++) acc += sA[ty][k] * sB[tx][k];
        __syncthreads();
    }
    const int i = bi + ty, j = bj + tx;
    const float r = scale * acc + ((i == j) ? EPSC : 0.f);
    if (which == 0) g_P[i * NXC + j] = r;
    else            g_H[i * NH + j]  = r;
}

// ---------------------------------------------------------------------------
// Build derived matrices. grid = 256 blocks (row i), 256 threads (col t)
// H1 = H[:256,:256], H2 = H[:256,256:], H4 = H[256:,256:]
// ---------------------------------------------------------------------------
__global__ void build_kernel(const float* __restrict__ Chi, const float* __restrict__ Y1,
                             const float* __restrict__ D12, const float* __restrict__ B2m)
{
    const int i = blockIdx.x;   // 0..255
    const int t = threadIdx.x;  // 0..255
    const float lam_inv = 2.0f / g_H[(256 + i) * NH + 256 + i]; // 1/(0.5*diag(H4))

    // RHS = [Y | Z], row i
    // Y = -0.5*(H1 + Y1 - Y1^T)   (ALPHA = 0)
    g_RHS[i * 512 + t] = -0.5f * (g_H[i * NH + t] + Y1[i * 256 + t] - Y1[t * 256 + i]);
    // Z = -H2 - Chi
    g_RHS[i * 512 + 256 + t] = -g_H[i * NH + 256 + t] - Chi[i * 256 + t];

    // Wv row q=i : C1[q][x] = lam_inv[q]*Chi[x][q] ; then D12[q][:]
    g_Wv[i * 320 + t] = lam_inv * Chi[t * 256 + i];
    if (t < 64) g_Wv[i * 320 + 256 + t] = D12[i * 64 + t];

    // D11[q=i][j=t] = (t<i) ? -lam_inv * H4[i][t] : 0 ; stored transposed
    g_D11t[t * 256 + i] = (t < i) ? (-lam_inv * g_H[(256 + i) * NH + 256 + t]) : 0.f;

    // B2 part of Wout
    if (t < 64) g_Wout[i * 576 + 512 + t] = B2m[i * 64 + t];
}

// ---------------------------------------------------------------------------
// Single-block Cholesky of g_P (256x256, SPD, no pivoting needed).
// Packed lower triangle in dynamic smem (32896 floats). 1024 threads, 4/row.
// ---------------------------------------------------------------------------
__global__ void chol_kernel()
{
    extern __shared__ float sL[];
    const int tid = threadIdx.x;

    for (int r = 0; r < 256; r++) {
        const int base = (r * (r + 1)) >> 1;
        for (int c = tid; c <= r; c += 1024) sL[base + c] = g_P[r * 256 + c];
    }
    __syncthreads();

    const int r = tid >> 2;       // row owned
    const int s = tid & 3;        // sub-lane within row
    const int rbase = (r * (r + 1)) >> 1;

    for (int j = 0; j < 256; j++) {
        const int jbase = (j * (j + 1)) >> 1;
        if (tid == 0) sL[jbase + j] = sqrtf(sL[jbase + j]);
        __syncthreads();
        const float invd = 1.0f / sL[jbase + j];
        if (s == 0 && r > j) sL[rbase + j] *= invd;
        __syncthreads();
        if (r > j) {
            const float lrj = sL[rbase + j];
            for (int c = j + 1 + s; c <= r; c += 4) {
                sL[rbase + c] -= lrj * sL[((c * (c + 1)) >> 1) + j];
            }
        }
        __syncthreads();
    }

    for (int rr = 0; rr < 256; rr++) {
        const int base = (rr * (rr + 1)) >> 1;
        for (int c = tid; c <= rr; c += 1024) g_P[rr * 256 + c] = sL[base + c];
    }
}

// ---------------------------------------------------------------------------
// Solve P M = [Y|Z] via L L^T (forward + backward substitution).
// 16 blocks x 32 RHS columns, 256 threads (8 k-partials x 32 cols).
// L staged packed in smem; RHS slice (256x32) in smem.
// Writes M = [A|B1] into g_Wout[:, 0:512].
// ---------------------------------------------------------------------------
__global__ void solve_kernel()
{
    extern __shared__ float sm[];
    float* sL   = sm;                       // 32896 floats
    float* sT   = sm + 32896;               // 256*32
    float* sRed = sT + 256 * 32;            // 8*32

    const int tid = threadIdx.x;
    const int c  = tid & 31;     // column within slice
    const int p  = tid >> 5;     // partial id (warp)
    const int c0 = blockIdx.x * 32;

    for (int r = 0; r < 256; r++) {
        const int base = (r * (r + 1)) >> 1;
        for (int cc = tid; cc <= r; cc += 256) sL[base + cc] = g_P[r * 256 + cc];
    }
    for (int i = p; i < 256; i += 8) sT[i * 32 + c] = g_RHS[i * 512 + c0 + c];
    __syncthreads();

    // forward: L T = RHS
    for (int i = 0; i < 256; i++) {
        const int base = (i * (i + 1)) >> 1;
        float part = 0.f;
        for (int j = p; j < i; j += 8) part += sL[base + j] * sT[j * 32 + c];
        sRed[p * 32 + c] = part;
        __syncthreads();
        if (p == 0) {
            float ssum = 0.f;
#pragma unroll
            for (int q = 0; q < 8; q++) ssum += sRed[q * 32 + c];
            sT[i * 32 + c] = (sT[i * 32 + c] - ssum) / sL[base + i];
        }
        __syncthreads();
    }

    // backward: L^T M = T
    for (int i = 255; i >= 0; i--) {
        float part = 0.f;
        for (int j = i + 1 + p; j < 256; j += 8)
            part += sL[((j * (j + 1)) >> 1) + i] * sT[j * 32 + c];
        sRed[p * 32 + c] = part;
        __syncthreads();
        if (p == 0) {
            float ssum = 0.f;
#pragma unroll
            for (int q = 0; q < 8; q++) ssum += sRed[q * 32 + c];
            sT[i * 32 + c] = (sT[i * 32 + c] - ssum) / sL[((i * (i + 1)) >> 1) + i];
        }
        __syncthreads();
    }

    for (int i = p; i < 256; i += 8) g_Wout[i * 576 + c0 + c] = sT[i * 32 + c];
}

// ---------------------------------------------------------------------------
// Fused v_base GEMM + tanh recurrence -> g_w.
// Block: 64 samples x full 256 cols. 256 threads, 8x8 micro-tiles
// (rows m0..m0+7, cols q0+32j). Dynamic smem: s_v[64][260] + tiles.
// ---------------------------------------------------------------------------
#define SV_LD 260
__global__ void __launch_bounds__(256) vw_kernel(const float* __restrict__ xi,
                                                 const float* __restrict__ u,
                                                 const float* __restrict__ bv)
{
    extern __shared__ float sh[];
    float* s_v = sh;                         // 64*260 = 16640
    float* s_a = sh + 64 * SV_LD;            // 8*64   = 512
    float* s_b = s_a + 8 * 64;               // 8*256  = 2048
    float* s_d = s_b + 8 * 256;              // 32*33  = 1056

    const int tid = threadIdx.x;
    const int s0  = blockIdx.x * 64;
    const int m0  = (tid >> 5) * 8;
    const int q0  = tid & 31;

    float acc[8][8];
#pragma unroll
    for (int i = 0; i < 8; i++)
#pragma unroll
        for (int j = 0; j < 8; j++) acc[i][j] = 0.f;

    // ---- v_base GEMM: [xi|u](64x320) @ Wv^T, N=256 ----
    for (int k0 = 0; k0 < 320; k0 += 8) {
        __syncthreads();
        if (tid < 128) {
            const int srow = tid & 63;
            const int h = (tid >> 6) & 1;
            const int k = k0 + 4 * h;
            float4 v;
            if (k < 256) v = *(const float4*)(xi + (size_t)(s0 + srow) * 256 + k);
            else         v = *(const float4*)(u  + (size_t)(s0 + srow) * 64 + (k - 256));
            s_a[(4 * h + 0) * 64 + srow] = v.x;
            s_a[(4 * h + 1) * 64 + srow] = v.y;
            s_a[(4 * h + 2) * 64 + srow] = v.z;
            s_a[(4 * h + 3) * 64 + srow] = v.w;
        }
        {
            const int q = tid;
            const float* p = g_Wv + q * 320 + k0;
            const float4 v0 = *(const float4*)p;
            const float4 v1 = *(const float4*)(p + 4);
            s_b[0 * 256 + q] = v0.x; s_b[1 * 256 + q] = v0.y;
            s_b[2 * 256 + q] = v0.z; s_b[3 * 256 + q] = v0.w;
            s_b[4 * 256 + q] = v1.x; s_b[5 * 256 + q] = v1.y;
            s_b[6 * 256 + q] = v1.z; s_b[7 * 256 + q] = v1.w;
        }
        __syncthreads();
#pragma unroll
        for (int kk = 0; kk < 8; kk++) {
            float a[8], b[8];
#pragma unroll
            for (int i = 0; i < 8; i++) a[i] = s_a[kk * 64 + m0 + i];
#pragma unroll
            for (int j = 0; j < 8; j++) b[j] = s_b[kk * 256 + q0 + 32 * j];
#pragma unroll
            for (int i = 0; i < 8; i++)
#pragma unroll
                for (int j = 0; j < 8; j++) acc[i][j] += a[i] * b[j];
        }
    }
    __syncthreads();

    // add bv, stash v into smem
#pragma unroll
    for (int j = 0; j < 8; j++) {
        const float bvj = bv[q0 + 32 * j];
#pragma unroll
        for (int i = 0; i < 8; i++)
            s_v[(m0 + i) * SV_LD + q0 + 32 * j] = acc[i][j] + bvj;
    }
    __syncthreads();

    // ---- recurrence: 8 panels of 32 columns ----
    for (int pb = 0; pb < 8; pb++) {
        const int qb = pb * 32;

        // stage diagonal D11 block: s_d[i][j] = D11[qb+i][qb+j]
        {
            const int ii = tid & 31;
            const int j0 = tid >> 5;
#pragma unroll
            for (int jj = 0; jj < 4; jj++) {
                const int j = j0 + jj * 8;
                s_d[ii * 33 + j] = g_D11t[(qb + j) * 256 + (qb + ii)];
            }
        }

        // cross-panel GEMM: v[:,qb..qb+31] += w[:,0..qb-1] @ D11_panel^T
        const int q = qb + (tid & 31);
        const int mm0 = (tid >> 5) * 8;
        float vc[8];
#pragma unroll
        for (int i = 0; i < 8; i++) vc[i] = 0.f;
        for (int j = 0; j < qb; j += 4) {
            const float d0 = g_D11t[(j + 0) * 256 + q];
            const float d1 = g_D11t[(j + 1) * 256 + q];
            const float d2 = g_D11t[(j + 2) * 256 + q];
            const float d3 = g_D11t[(j + 3) * 256 + q];
#pragma unroll
            for (int i = 0; i < 8; i++) {
                const float4 wv = *(const float4*)&s_v[(mm0 + i) * SV_LD + j];
                vc[i] += wv.x * d0 + wv.y * d1 + wv.z * d2 + wv.w * d3;
            }
        }
        __syncthreads();
#pragma unroll
        for (int i = 0; i < 8; i++) s_v[(mm0 + i) * SV_LD + q] += vc[i];
        __syncthreads();

        // sequential diagonal scan: thread t owns sample t (t < 64)
        if (tid < 64) {
            float wreg[32];
            float* vrow = &s_v[tid * SV_LD + qb];
#pragma unroll
            for (int i = 0; i < 32; i++) {
                float v = vrow[i];
#pragma unroll
                for (int j = 0; j < i; j++) v += wreg[j] * s_d[i * 33 + j];
                const float w = tanhf(v);
                wreg[i] = w;
                vrow[i] = w;
            }
        }
        __syncthreads();
    }

    // write w to global (coalesced)
    for (int idx = tid; idx < 64 * 256; idx += 256) {
        const int srow = idx >> 8;
        const int q = idx & 255;
        g_w[(size_t)(s0 + srow) * 256 + q] = s_v[srow * SV_LD + q];
    }
}

// ---------------------------------------------------------------------------
// Output GEMM: out = [xi|w|u](64x576) @ Wout^T + bx. Same tiling as vw_kernel.
// ---------------------------------------------------------------------------
__global__ void __launch_bounds__(256) out_kernel(const float* __restrict__ xi,
                                                  const float* __restrict__ u,
                                                  const float* __restrict__ bx,
                                                  float* __restrict__ out)
{
    __shared__ float s_a[8 * 64];
    __shared__ float s_b[8 * 256];

    const int tid = threadIdx.x;
    const int s0  = blockIdx.x * 64;
    const int m0  = (tid >> 5) * 8;
    const int q0  = tid & 31;

    float acc[8][8];
#pragma unroll
    for (int i = 0; i < 8; i++)
#pragma unroll
        for (int j = 0; j < 8; j++) acc[i][j] = 0.f;

    for (int k0 = 0; k0 < 576; k0 += 8) {
        __syncthreads();
        if (tid < 128) {
            const int srow = tid & 63;
            const int h = (tid >> 6) & 1;
            const int k = k0 + 4 * h;
            float4 v;
            if (k < 256)      v = *(const float4*)(xi  + (size_t)(s0 + srow) * 256 + k);
            else if (k < 512) v = *(const float4*)(g_w + (size_t)(s0 + srow) * 256 + (k - 256));
            else              v = *(const float4*)(u   + (size_t)(s0 + srow) * 64 + (k - 512));
            s_a[(4 * h + 0) * 64 + srow] = v.x;
            s_a[(4 * h + 1) * 64 + srow] = v.y;
            s_a[(4 * h + 2) * 64 + srow] = v.z;
            s_a[(4 * h + 3) * 64 + srow] = v.w;
        }
        {
            const int x = tid;
            const float* p = g_Wout + x * 576 + k0;
            const float4 v0 = *(const float4*)p;
            const float4 v1 = *(const float4*)(p + 4);
            s_b[0 * 256 + x] = v0.x; s_b[1 * 256 + x] = v0.y;
            s_b[2 * 256 + x] = v0.z; s_b[3 * 256 + x] = v0.w;
            s_b[4 * 256 + x] = v1.x; s_b[5 * 256 + x] = v1.y;
            s_b[6 * 256 + x] = v1.z; s_b[7 * 256 + x] = v1.w;
        }
        __syncthreads();
#pragma unroll
        for (int kk = 0; kk < 8; kk++) {
            float a[8], b[8];
#pragma unroll
            for (int i = 0; i < 8; i++) a[i] = s_a[kk * 64 + m0 + i];
#pragma unroll
            for (int j = 0; j < 8; j++) b[j] = s_b[kk * 256 + q0 + 32 * j];
#pragma unroll
            for (int i = 0; i < 8; i++)
#pragma unroll
                for (int j = 0; j < 8; j++) acc[i][j] += a[i] * b[j];
        }
    }

#pragma unroll
    for (int j = 0; j < 8; j++) {
        const int x = q0 + 32 * j;
        const float bxv = bx[x];
#pragma unroll
        for (int i = 0; i < 8; i++)
            out[(size_t)(s0 + m0 + i) * 256 + x] = acc[i][j] + bxv;
    }
}

// ---------------------------------------------------------------------------
// Host launcher
// ---------------------------------------------------------------------------
extern "C" void kernel_launch(void* const* d_in, const int* in_sizes, int n_in,
                              void* d_out, int out_size)
{
    const float* xi    = (const float*)d_in[1];
    const float* u     = (const float*)d_in[2];
    const float* Pstar = (const float*)d_in[3];
    const float* Chi   = (const float*)d_in[4];
    const float* Y1    = (const float*)d_in[5];
    const float* B2m   = (const float*)d_in[6];
    const float* D12   = (const float*)d_in[7];
    const float* X     = (const float*)d_in[8];
    const float* bx    = (const float*)d_in[9];
    const float* bv    = (const float*)d_in[10];
    float* out = (float*)d_out;

    const int CHOL_SMEM  = 32896 * 4;                       // 131584
    const int SOLVE_SMEM = (32896 + 256 * 32 + 8 * 32) * 4; // 165376
    const int VW_SMEM    = (64 * SV_LD + 8 * 64 + 8 * 256 + 32 * 33) * 4; // 81024

    cudaFuncSetAttribute(chol_kernel,  cudaFuncAttributeMaxDynamicSharedMemorySize, CHOL_SMEM);
    cudaFuncSetAttribute(solve_kernel, cudaFuncAttributeMaxDynamicSharedMemorySize, SOLVE_SMEM);
    cudaFuncSetAttribute(vw_kernel,    cudaFuncAttributeMaxDynamicSharedMemorySize, VW_SMEM);

    gram_kernel<<<dim3(8, 8),   dim3(32, 32)>>>(Pstar, 256, 0.5f, 0);
    gram_kernel<<<dim3(16, 16), dim3(32, 32)>>>(X,     512, 1.0f, 1);
    build_kernel<<<256, 256>>>(Chi, Y1, D12, B2m);
    chol_kernel<<<1, 1024, CHOL_SMEM>>>();
    solve_kernel<<<16, 256, SOLVE_SMEM>>>();
    vw_kernel<<<NBATCH / 64, 256, VW_SMEM>>>(xi, u, bv);
    out_kernel<<<NBATCH / 64, 256>>>(xi, u, bx, out);
}

// round 3
// speedup vs baseline: 1.0004x; 1.0004x over previous
#include <cuda_runtime.h>
#include <math.h>
#include <stdint.h>

// Problem constants
#define NXC   256
#define NQC   256
#define NUC   64
#define NBATCH 32768
#define EPSC  1e-3f
#define NH    320   // NX + NQ... actually NX+NQ=512? No: H is (NX+NQ)=(256+64?) -- see below
// NOTE: X is (NX+NQ) x (NX+NQ) = 320x320?  NX=256, NQ=256 -> 512?  Recheck:
// Reference: NX, NQ, NU, NY = (256, 256, 64, 64); X: (NX+NQ, NX+NQ) = (512, 512).
// CORRECTION: NH must be 512.
#undef NH
#define NH 512

// ---------------------------------------------------------------------------
// Device scratch (static allocations only — no cudaMalloc allowed)
// ---------------------------------------------------------------------------
__device__ float g_P[NXC * NXC];          // P, then Cholesky factor L (lower)
__device__ float g_H[NH * NH];            // H = X X^T + eps I  (512x512)
__device__ float g_RHS[NXC * 512];        // [Y | Z]  (256 x 512)
__device__ float g_Wv[NQC * 320];         // [C1 | D12] rows q, K = 256+64
__device__ float g_D11t[NQC * NQC];       // D11 transposed: g_D11t[j*256+q] = D11[q][j]
__device__ float g_Wout[NXC * 576];       // [A | B1 | B2] rows x, K = 256+256+64
__device__ float g_w[(size_t)NBATCH * NQC];

// ---------------------------------------------------------------------------
// Gram kernel: out = scale * M M^T + eps I   (which==0 -> g_P(256), else g_H(512))
// ---------------------------------------------------------------------------
__global__ void gram_kernel(const float* __restrict__ M, int n, float scale, int which)
{
    __shared__ float sA[32][33];
    __shared__ float sB[32][33];
    const int tx = threadIdx.x, ty = threadIdx.y;
    const int bi = blockIdx.y * 32, bj = blockIdx.x * 32;
    float acc = 0.f;
    for (int k0 = 0; k0 < n; k0 += 32) {
        sA[ty][tx] = M[(bi + ty) * n + k0 + tx];
        sB[ty][tx] = M[(bj + ty) * n + k0 + tx];
        __syncthreads();
#pragma unroll
        for (int k = 0; k < 32; k++) acc += sA[ty][k] * sB[tx][k];
        __syncthreads();
    }
    const int i = bi + ty, j = bj + tx;
    const float r = scale * acc + ((i == j) ? EPSC : 0.f);
    if (which == 0) g_P[i * NXC + j] = r;
    else            g_H[i * NH + j]  = r;
}

// ---------------------------------------------------------------------------
// Build derived matrices. grid = 256 blocks (row i), 256 threads (col t)
// H1 = H[:256,:256], H2 = H[:256,256:], H4 = H[256:,256:]
// ---------------------------------------------------------------------------
__global__ void build_kernel(const float* __restrict__ Chi, const float* __restrict__ Y1,
                             const float* __restrict__ D12, const float* __restrict__ B2m)
{
    const int i = blockIdx.x;   // 0..255
    const int t = threadIdx.x;  // 0..255
    const float lam_inv = 2.0f / g_H[(256 + i) * NH + 256 + i]; // 1/(0.5*diag(H4))

    // RHS = [Y | Z], row i
    // Y = -0.5*(H1 + Y1 - Y1^T)   (ALPHA = 0)
    g_RHS[i * 512 + t] = -0.5f * (g_H[i * NH + t] + Y1[i * 256 + t] - Y1[t * 256 + i]);
    // Z = -H2 - Chi
    g_RHS[i * 512 + 256 + t] = -g_H[i * NH + 256 + t] - Chi[i * 256 + t];

    // Wv row q=i : C1[q][x] = lam_inv[q]*Chi[x][q] ; then D12[q][:]
    g_Wv[i * 320 + t] = lam_inv * Chi[t * 256 + i];
    if (t < 64) g_Wv[i * 320 + 256 + t] = D12[i * 64 + t];

    // D11[q=i][j=t] = (t<i) ? -lam_inv * H4[i][t] : 0 ; stored transposed
    g_D11t[t * 256 + i] = (t < i) ? (-lam_inv * g_H[(256 + i) * NH + 256 + t]) : 0.f;

    // B2 part of Wout
    if (t < 64) g_Wout[i * 576 + 512 + t] = B2m[i * 64 + t];
}

// ---------------------------------------------------------------------------
// Single-block Cholesky of g_P (256x256, SPD, no pivoting needed).
// Packed lower triangle in dynamic smem (32896 floats). 1024 threads, 4/row.
// ---------------------------------------------------------------------------
__global__ void chol_kernel()
{
    extern __shared__ float sL[];
    const int tid = threadIdx.x;

    for (int r = 0; r < 256; r++) {
        const int base = (r * (r + 1)) >> 1;
        for (int c = tid; c <= r; c += 1024) sL[base + c] = g_P[r * 256 + c];
    }
    __syncthreads();

    const int r = tid >> 2;       // row owned
    const int s = tid & 3;        // sub-lane within row
    const int rbase = (r * (r + 1)) >> 1;

    for (int j = 0; j < 256; j++) {
        const int jbase = (j * (j + 1)) >> 1;
        if (tid == 0) sL[jbase + j] = sqrtf(sL[jbase + j]);
        __syncthreads();
        const float invd = 1.0f / sL[jbase + j];
        if (s == 0 && r > j) sL[rbase + j] *= invd;
        __syncthreads();
        if (r > j) {
            const float lrj = sL[rbase + j];
            for (int c = j + 1 + s; c <= r; c += 4) {
                sL[rbase + c] -= lrj * sL[((c * (c + 1)) >> 1) + j];
            }
        }
        __syncthreads();
    }

    for (int rr = 0; rr < 256; rr++) {
        const int base = (rr * (rr + 1)) >> 1;
        for (int c = tid; c <= rr; c += 1024) g_P[rr * 256 + c] = sL[base + c];
    }
}

// ---------------------------------------------------------------------------
// Solve P M = [Y|Z] via L L^T (forward + backward substitution).
// 16 blocks x 32 RHS columns, 256 threads (8 k-partials x 32 cols).
// L staged packed in smem; RHS slice (256x32) in smem.
// Writes M = [A|B1] into g_Wout[:, 0:512].
// ---------------------------------------------------------------------------
__global__ void solve_kernel()
{
    extern __shared__ float sm[];
    float* sL   = sm;                       // 32896 floats
    float* sT   = sm + 32896;               // 256*32
    float* sRed = sT + 256 * 32;            // 8*32

    const int tid = threadIdx.x;
    const int c  = tid & 31;     // column within slice
    const int p  = tid >> 5;     // partial id (warp)
    const int c0 = blockIdx.x * 32;

    for (int r = 0; r < 256; r++) {
        const int base = (r * (r + 1)) >> 1;
        for (int cc = tid; cc <= r; cc += 256) sL[base + cc] = g_P[r * 256 + cc];
    }
    for (int i = p; i < 256; i += 8) sT[i * 32 + c] = g_RHS[i * 512 + c0 + c];
    __syncthreads();

    // forward: L T = RHS
    for (int i = 0; i < 256; i++) {
        const int base = (i * (i + 1)) >> 1;
        float part = 0.f;
        for (int j = p; j < i; j += 8) part += sL[base + j] * sT[j * 32 + c];
        sRed[p * 32 + c] = part;
        __syncthreads();
        if (p == 0) {
            float ssum = 0.f;
#pragma unroll
            for (int q = 0; q < 8; q++) ssum += sRed[q * 32 + c];
            sT[i * 32 + c] = (sT[i * 32 + c] - ssum) / sL[base + i];
        }
        __syncthreads();
    }

    // backward: L^T M = T
    for (int i = 255; i >= 0; i--) {
        float part = 0.f;
        for (int j = i + 1 + p; j < 256; j += 8)
            part += sL[((j * (j + 1)) >> 1) + i] * sT[j * 32 + c];
        sRed[p * 32 + c] = part;
        __syncthreads();
        if (p == 0) {
            float ssum = 0.f;
#pragma unroll
            for (int q = 0; q < 8; q++) ssum += sRed[q * 32 + c];
            sT[i * 32 + c] = (sT[i * 32 + c] - ssum) / sL[((i * (i + 1)) >> 1) + i];
        }
        __syncthreads();
    }

    for (int i = p; i < 256; i += 8) g_Wout[i * 576 + c0 + c] = sT[i * 32 + c];
}

// ---------------------------------------------------------------------------
// Fused v_base GEMM + tanh recurrence -> g_w.
// Block: 64 samples x full 256 cols. 256 threads, 8x8 micro-tiles
// (rows m0..m0+7, cols q0+32j). Dynamic smem: s_v[64][260] + tiles.
// ---------------------------------------------------------------------------
#define SV_LD 260
__global__ void __launch_bounds__(256) vw_kernel(const float* __restrict__ xi,
                                                 const float* __restrict__ u,
                                                 const float* __restrict__ bv)
{
    extern __shared__ float sh[];
    float* s_v = sh;                         // 64*260 = 16640
    float* s_a = sh + 64 * SV_LD;            // 8*64   = 512
    float* s_b = s_a + 8 * 64;               // 8*256  = 2048
    float* s_d = s_b + 8 * 256;              // 32*33  = 1056

    const int tid = threadIdx.x;
    const int s0  = blockIdx.x * 64;
    const int m0  = (tid >> 5) * 8;
    const int q0  = tid & 31;

    float acc[8][8];
#pragma unroll
    for (int i = 0; i < 8; i++)
#pragma unroll
        for (int j = 0; j < 8; j++) acc[i][j] = 0.f;

    // ---- v_base GEMM: [xi|u](64x320) @ Wv^T, N=256 ----
    for (int k0 = 0; k0 < 320; k0 += 8) {
        __syncthreads();
        if (tid < 128) {
            const int srow = tid & 63;
            const int h = (tid >> 6) & 1;
            const int k = k0 + 4 * h;
            float4 v;
            if (k < 256) v = *(const float4*)(xi + (size_t)(s0 + srow) * 256 + k);
            else         v = *(const float4*)(u  + (size_t)(s0 + srow) * 64 + (k - 256));
            s_a[(4 * h + 0) * 64 + srow] = v.x;
            s_a[(4 * h + 1) * 64 + srow] = v.y;
            s_a[(4 * h + 2) * 64 + srow] = v.z;
            s_a[(4 * h + 3) * 64 + srow] = v.w;
        }
        {
            const int q = tid;
            const float* p = g_Wv + q * 320 + k0;
            const float4 v0 = *(const float4*)p;
            const float4 v1 = *(const float4*)(p + 4);
            s_b[0 * 256 + q] = v0.x; s_b[1 * 256 + q] = v0.y;
            s_b[2 * 256 + q] = v0.z; s_b[3 * 256 + q] = v0.w;
            s_b[4 * 256 + q] = v1.x; s_b[5 * 256 + q] = v1.y;
            s_b[6 * 256 + q] = v1.z; s_b[7 * 256 + q] = v1.w;
        }
        __syncthreads();
#pragma unroll
        for (int kk = 0; kk < 8; kk++) {
            float a[8], b[8];
#pragma unroll
            for (int i = 0; i < 8; i++) a[i] = s_a[kk * 64 + m0 + i];
#pragma unroll
            for (int j = 0; j < 8; j++) b[j] = s_b[kk * 256 + q0 + 32 * j];
#pragma unroll
            for (int i = 0; i < 8; i++)
#pragma unroll
                for (int j = 0; j < 8; j++) acc[i][j] += a[i] * b[j];
        }
    }
    __syncthreads();

    // add bv, stash v into smem
#pragma unroll
    for (int j = 0; j < 8; j++) {
        const float bvj = bv[q0 + 32 * j];
#pragma unroll
        for (int i = 0; i < 8; i++)
            s_v[(m0 + i) * SV_LD + q0 + 32 * j] = acc[i][j] + bvj;
    }
    __syncthreads();

    // ---- recurrence: 8 panels of 32 columns ----
    for (int pb = 0; pb < 8; pb++) {
        const int qb = pb * 32;

        // stage diagonal D11 block: s_d[i][j] = D11[qb+i][qb+j]
        {
            const int ii = tid & 31;
            const int j0 = tid >> 5;
#pragma unroll
            for (int jj = 0; jj < 4; jj++) {
                const int j = j0 + jj * 8;
                s_d[ii * 33 + j] = g_D11t[(qb + j) * 256 + (qb + ii)];
            }
        }

        // cross-panel GEMM: v[:,qb..qb+31] += w[:,0..qb-1] @ D11_panel^T
        const int q = qb + (tid & 31);
        const int mm0 = (tid >> 5) * 8;
        float vc[8];
#pragma unroll
        for (int i = 0; i < 8; i++) vc[i] = 0.f;
        for (int j = 0; j < qb; j += 4) {
            const float d0 = g_D11t[(j + 0) * 256 + q];
            const float d1 = g_D11t[(j + 1) * 256 + q];
            const float d2 = g_D11t[(j + 2) * 256 + q];
            const float d3 = g_D11t[(j + 3) * 256 + q];
#pragma unroll
            for (int i = 0; i < 8; i++) {
                const float4 wv = *(const float4*)&s_v[(mm0 + i) * SV_LD + j];
                vc[i] += wv.x * d0 + wv.y * d1 + wv.z * d2 + wv.w * d3;
            }
        }
        __syncthreads();
#pragma unroll
        for (int i = 0; i < 8; i++) s_v[(mm0 + i) * SV_LD + q] += vc[i];
        __syncthreads();

        // sequential diagonal scan: thread t owns sample t (t < 64)
        if (tid < 64) {
            float wreg[32];
            float* vrow = &s_v[tid * SV_LD + qb];
#pragma unroll
            for (int i = 0; i < 32; i++) {
                float v = vrow[i];
#pragma unroll
                for (int j = 0; j < i; j++) v += wreg[j] * s_d[i * 33 + j];
                const float w = tanhf(v);
                wreg[i] = w;
                vrow[i] = w;
            }
        }
        __syncthreads();
    }

    // write w to global (coalesced)
    for (int idx = tid; idx < 64 * 256; idx += 256) {
        const int srow = idx >> 8;
        const int q = idx & 255;
        g_w[(size_t)(s0 + srow) * 256 + q] = s_v[srow * SV_LD + q];
    }
}

// ---------------------------------------------------------------------------
// Output GEMM: out = [xi|w|u](64x576) @ Wout^T + bx. Same tiling as vw_kernel.
// ---------------------------------------------------------------------------
__global__ void __launch_bounds__(256) out_kernel(const float* __restrict__ xi,
                                                  const float* __restrict__ u,
                                                  const float* __restrict__ bx,
                                                  float* __restrict__ out)
{
    __shared__ float s_a[8 * 64];
    __shared__ float s_b[8 * 256];

    const int tid = threadIdx.x;
    const int s0  = blockIdx.x * 64;
    const int m0  = (tid >> 5) * 8;
    const int q0  = tid & 31;

    float acc[8][8];
#pragma unroll
    for (int i = 0; i < 8; i++)
#pragma unroll
        for (int j = 0; j < 8; j++) acc[i][j] = 0.f;

    for (int k0 = 0; k0 < 576; k0 += 8) {
        __syncthreads();
        if (tid < 128) {
            const int srow = tid & 63;
            const int h = (tid >> 6) & 1;
            const int k = k0 + 4 * h;
            float4 v;
            if (k < 256)      v = *(const float4*)(xi  + (size_t)(s0 + srow) * 256 + k);
            else if (k < 512) v = *(const float4*)(g_w + (size_t)(s0 + srow) * 256 + (k - 256));
            else              v = *(const float4*)(u   + (size_t)(s0 + srow) * 64 + (k - 512));
            s_a[(4 * h + 0) * 64 + srow] = v.x;
            s_a[(4 * h + 1) * 64 + srow] = v.y;
            s_a[(4 * h + 2) * 64 + srow] = v.z;
            s_a[(4 * h + 3) * 64 + srow] = v.w;
        }
        {
            const int x = tid;
            const float* p = g_Wout + x * 576 + k0;
            const float4 v0 = *(const float4*)p;
            const float4 v1 = *(const float4*)(p + 4);
            s_b[0 * 256 + x] = v0.x; s_b[1 * 256 + x] = v0.y;
            s_b[2 * 256 + x] = v0.z; s_b[3 * 256 + x] = v0.w;
            s_b[4 * 256 + x] = v1.x; s_b[5 * 256 + x] = v1.y;
            s_b[6 * 256 + x] = v1.z; s_b[7 * 256 + x] = v1.w;
        }
        __syncthreads();
#pragma unroll
        for (int kk = 0; kk < 8; kk++) {
            float a[8], b[8];
#pragma unroll
            for (int i = 0; i < 8; i++) a[i] = s_a[kk * 64 + m0 + i];
#pragma unroll
            for (int j = 0; j < 8; j++) b[j] = s_b[kk * 256 + q0 + 32 * j];
#pragma unroll
            for (int i = 0; i < 8; i++)
#pragma unroll
                for (int j = 0; j < 8; j++) acc[i][j] += a[i] * b[j];
        }
    }

#pragma unroll
    for (int j = 0; j < 8; j++) {
        const int x = q0 + 32 * j;
        const float bxv = bx[x];
#pragma unroll
        for (int i = 0; i < 8; i++)
            out[(size_t)(s0 + m0 + i) * 256 + x] = acc[i][j] + bxv;
    }
}

// ---------------------------------------------------------------------------
// Host launcher
// ---------------------------------------------------------------------------
extern "C" void kernel_launch(void* const* d_in, const int* in_sizes, int n_in,
                              void* d_out, int out_size)
{
    const float* xi    = (const float*)d_in[1];
    const float* u     = (const float*)d_in[2];
    const float* Pstar = (const float*)d_in[3];
    const float* Chi   = (const float*)d_in[4];
    const float* Y1    = (const float*)d_in[5];
    const float* B2m   = (const float*)d_in[6];
    const float* D12   = (const float*)d_in[7];
    const float* X     = (const float*)d_in[8];
    const float* bx    = (const float*)d_in[9];
    const float* bv    = (const float*)d_in[10];
    float* out = (float*)d_out;

    const int CHOL_SMEM  = 32896 * 4;                       // 131584
    const int SOLVE_SMEM = (32896 + 256 * 32 + 8 * 32) * 4; // 165376
    const int VW_SMEM    = (64 * SV_LD + 8 * 64 + 8 * 256 + 32 * 33) * 4; // 81024

    cudaFuncSetAttribute(chol_kernel,  cudaFuncAttributeMaxDynamicSharedMemorySize, CHOL_SMEM);
    cudaFuncSetAttribute(solve_kernel, cudaFuncAttributeMaxDynamicSharedMemorySize, SOLVE_SMEM);
    cudaFuncSetAttribute(vw_kernel,    cudaFuncAttributeMaxDynamicSharedMemorySize, VW_SMEM);

    gram_kernel<<<dim3(8, 8),   dim3(32, 32)>>>(Pstar, 256, 0.5f, 0);
    gram_kernel<<<dim3(16, 16), dim3(32, 32)>>>(X,     512, 1.0f, 1);
    build_kernel<<<256, 256>>>(Chi, Y1, D12, B2m);
    chol_kernel<<<1, 1024, CHOL_SMEM>>>();
    solve_kernel<<<16, 256, SOLVE_SMEM>>>();
    vw_kernel<<<NBATCH / 64, 256, VW_SMEM>>>(xi, u, bv);
    out_kernel<<<NBATCH / 64, 256>>>(xi, u, bx, out);
}